// round 2
// baseline (speedup 1.0000x reference)
#include <cuda_runtime.h>

// ---------------- problem constants ----------------
#define HH 512
#define WW 512
#define NB 16
#define OH 510
#define OW 510

#define TOX 102          // output tile x  (5 * 102 = 510, exact)
#define TOY 30           // output tile y  (17 * 30 = 510, exact)
#define TIX 104          // input tile x (halo +2)
#define TIY 32           // input tile y (halo +2)
#define NTHREADS 256

typedef unsigned long long u64;

// ---------------- packed f32x2 helpers (Blackwell) ----------------
__device__ __forceinline__ u64 fma2(u64 a, u64 b, u64 c) {
    u64 d;
    asm("fma.rn.f32x2 %0, %1, %2, %3;" : "=l"(d) : "l"(a), "l"(b), "l"(c));
    return d;
}
__device__ __forceinline__ u64 mul2(u64 a, u64 b) {
    u64 d;
    asm("mul.rn.f32x2 %0, %1, %2;" : "=l"(d) : "l"(a), "l"(b));
    return d;
}
// leaky_relu(x) = 0.55*x + 0.45*|x|   (== x for x>=0, 0.1*x for x<0)
__device__ __forceinline__ u64 lrelu2(u64 x) {
    const u64 C055 = 0x3F0CCCCD3F0CCCCDull;   // (0.55f, 0.55f)
    const u64 C045 = 0x3EE666663EE66666ull;   // (0.45f, 0.45f)
    const u64 MASK = 0x7FFFFFFF7FFFFFFFull;
    return fma2(x & MASK, C045, mul2(x, C055));
}

// ---------------- shared-memory weight layout (f32x2-duplicated) ----------------
// Each layer row = CI weights then the bias, all duplicated (w,w) as u64.
#define OFF1 0        // L1: 24 rows * 5
#define OFF2 120      // L2: 27 rows * 25
#define OFF3 795      // L3: 27 rows * 28
#define OFF4 1551
#define OFF5 2307
#define OFF6 3063
#define OFF7 3819     // L7: 9 rows * 28
#define TOTW 4071     // total u64 chain params

#define W8S_OFF  (TOTW * 8)            // 32568 bytes
#define HS_OFF   (W8S_OFF + 246 * 4)   // 33552 bytes (8B aligned)
#define HS_PLANE (TIY * TIX)           // 3328 floats per channel
#define SMEM_TOTAL (HS_OFF + 9 * HS_PLANE * 4)   // 153360 bytes

__device__ __forceinline__ void fill_layer(u64* dst, const float* __restrict__ w,
                                           const float* __restrict__ b,
                                           int CI, int CO, int tid) {
    int n = CO * (CI + 1);
    for (int idx = tid; idx < n; idx += NTHREADS) {
        int o = idx / (CI + 1), c = idx % (CI + 1);
        float v = (c < CI) ? w[o * CI + c] : b[o];
        unsigned int u = __float_as_uint(v);
        dst[idx] = (((u64)u) << 32) | u;
    }
}

template <int CI, int CO, bool ACT>
__device__ __forceinline__ void pw(const u64* __restrict__ ws,
                                   const u64* __restrict__ in, u64* __restrict__ out) {
#pragma unroll
    for (int o = 0; o < CO; o++) {
        const u64* r = ws + o * (CI + 1);
        u64 acc = r[CI];                    // bias (pre-duplicated)
#pragma unroll
        for (int i = 0; i < CI; i++) acc = fma2(in[i], r[i], acc);
        out[o] = ACT ? lrelu2(acc) : acc;
    }
}

__global__ void __launch_bounds__(NTHREADS, 1)
fusion_kernel(const float* __restrict__ x,
              const float* __restrict__ w1, const float* __restrict__ b1,
              const float* __restrict__ w2, const float* __restrict__ b2,
              const float* __restrict__ w3, const float* __restrict__ b3,
              const float* __restrict__ w4, const float* __restrict__ b4,
              const float* __restrict__ w5, const float* __restrict__ b5,
              const float* __restrict__ w6, const float* __restrict__ b6,
              const float* __restrict__ w7, const float* __restrict__ b7,
              const float* __restrict__ w8, const float* __restrict__ b8,
              float* __restrict__ out) {
    extern __shared__ char smem[];
    u64*   wsm = (u64*)smem;
    float* w8s = (float*)(smem + W8S_OFF);
    float* hs  = (float*)(smem + HS_OFF);

    const int tid = threadIdx.x;

    // ---- stage weights into SMEM (duplicated pairs for the chain) ----
    fill_layer(wsm + OFF1, w1, b1, 4, 24, tid);
    fill_layer(wsm + OFF2, w2, b2, 24, 27, tid);
    fill_layer(wsm + OFF3, w3, b3, 27, 27, tid);
    fill_layer(wsm + OFF4, w4, b4, 27, 27, tid);
    fill_layer(wsm + OFF5, w5, b5, 27, 27, tid);
    fill_layer(wsm + OFF6, w6, b6, 27, 27, tid);
    fill_layer(wsm + OFF7, w7, b7, 27,  9, tid);
    for (int i = tid; i < 243; i += NTHREADS) w8s[i] = w8[i];
    if (tid < 3) w8s[243 + tid] = b8[tid];
    __syncthreads();

    const int x0 = blockIdx.x * TOX;
    const int y0 = blockIdx.y * TOY;
    const int b  = blockIdx.z;
    const float* xb = x + (size_t)b * 4 * HH * WW;

    // ---- pointwise chain on (TIX x TIY) input region, 2 pixels per thread-iter ----
    const int NPAIRS = (TIX / 2) * TIY;      // 1664
    for (int p = tid; p < NPAIRS; p += NTHREADS) {
        int row = p / (TIX / 2);
        int cp  = p % (TIX / 2);
        int gy = y0 + row, gx = x0 + cp * 2;

        u64 a[27], c[27];
        const float* px0 = xb + (size_t)gy * WW + gx;
#pragma unroll
        for (int ch = 0; ch < 4; ch++)
            a[ch] = *(const u64*)(px0 + (size_t)ch * HH * WW);

        pw<4, 24, true >(wsm + OFF1, a, c);
        pw<24, 27, true >(wsm + OFF2, c, a);
        pw<27, 27, true >(wsm + OFF3, a, c);
        pw<27, 27, true >(wsm + OFF4, c, a);
        pw<27, 27, true >(wsm + OFF5, a, c);
        pw<27, 27, true >(wsm + OFF6, c, a);
        pw<27, 9,  false>(wsm + OFF7, a, c);

#pragma unroll
        for (int ch = 0; ch < 9; ch++)
            *(u64*)&hs[ch * HS_PLANE + row * TIX + cp * 2] = c[ch];
    }
    __syncthreads();

    // ---- 3x3 VALID conv 9 -> 3 from SMEM ----
    const size_t obase = (size_t)b * 3 * OH * OW;
    const float bb0 = w8s[243], bb1 = w8s[244], bb2 = w8s[245];
    for (int q = tid; q < TOX * TOY; q += NTHREADS) {
        int oy = q / TOX, ox = q % TOX;
        float s0 = bb0, s1 = bb1, s2 = bb2;
#pragma unroll
        for (int ci = 0; ci < 9; ci++) {
#pragma unroll
            for (int ky = 0; ky < 3; ky++) {
                const float* hp = &hs[ci * HS_PLANE + (oy + ky) * TIX + ox];
#pragma unroll
                for (int kx = 0; kx < 3; kx++) {
                    float v = hp[kx];
                    int wi = (ci * 3 + ky) * 3 + kx;
                    s0 = fmaf(v, w8s[wi], s0);
                    s1 = fmaf(v, w8s[81 + wi], s1);
                    s2 = fmaf(v, w8s[162 + wi], s2);
                }
            }
        }
        int gy = y0 + oy, gx = x0 + ox;
        size_t o = obase + (size_t)gy * OW + gx;
        out[o]                       = s0;
        out[o + (size_t)OH * OW]     = s1;
        out[o + (size_t)2 * OH * OW] = s2;
    }
}

extern "C" void kernel_launch(void* const* d_in, const int* in_sizes, int n_in,
                              void* d_out, int out_size) {
    (void)in_sizes; (void)n_in; (void)out_size;
    const float* x  = (const float*)d_in[0];
    const float* w1 = (const float*)d_in[1];
    const float* b1 = (const float*)d_in[2];
    const float* w2 = (const float*)d_in[3];
    const float* b2 = (const float*)d_in[4];
    const float* w3 = (const float*)d_in[5];
    const float* b3 = (const float*)d_in[6];
    const float* w4 = (const float*)d_in[7];
    const float* b4 = (const float*)d_in[8];
    const float* w5 = (const float*)d_in[9];
    const float* b5 = (const float*)d_in[10];
    const float* w6 = (const float*)d_in[11];
    const float* b6 = (const float*)d_in[12];
    const float* w7 = (const float*)d_in[13];
    const float* b7 = (const float*)d_in[14];
    const float* w8 = (const float*)d_in[15];
    const float* b8 = (const float*)d_in[16];
    float* out = (float*)d_out;

    cudaFuncSetAttribute(fusion_kernel,
                         cudaFuncAttributeMaxDynamicSharedMemorySize, SMEM_TOTAL);
    dim3 grid(OW / TOX, OH / TOY, NB);   // (5, 17, 16)
    fusion_kernel<<<grid, NTHREADS, SMEM_TOTAL>>>(
        x, w1, b1, w2, b2, w3, b3, w4, b4, w5, b5, w6, b6, w7, b7, w8, b8, out);
}

// round 3
// speedup vs baseline: 1.0131x; 1.0131x over previous
#include <cuda_runtime.h>

// ---------------- problem constants ----------------
#define HH 512
#define WW 512
#define NB 16
#define OH 510
#define OW 510

#define TOX 102          // output tile x  (5 * 102 = 510, exact)
#define TOY 30           // output tile y  (17 * 30 = 510, exact)
#define TIX 104          // input tile x (halo +2)
#define TIY 32           // input tile y (halo +2)
#define NTHREADS 384

typedef unsigned long long u64;

// ---------------- packed f32x2 helpers (Blackwell) ----------------
__device__ __forceinline__ u64 fma2(u64 a, u64 b, u64 c) {
    u64 d;
    asm("fma.rn.f32x2 %0, %1, %2, %3;" : "=l"(d) : "l"(a), "l"(b), "l"(c));
    return d;
}
__device__ __forceinline__ u64 pack2(float lo, float hi) {
    u64 d;
    asm("mov.b64 %0, {%1, %2};" : "=l"(d) : "f"(lo), "f"(hi));
    return d;
}
__device__ __forceinline__ float sum2(u64 v) {   // lo + hi
    float lo, hi;
    asm("mov.b64 {%0, %1}, %2;" : "=f"(lo), "=f"(hi) : "l"(v));
    return lo + hi;
}
// leaky_relu(s) = 0.55*s + 0.45*|s|  (rel err ~2e-7, verified in round 2)
__device__ __forceinline__ float lrelu(float s) {
    return fmaf(fabsf(s), 0.45f, 0.55f * s);
}

// ---------------- SMEM weight layout (channel-pair packed) ----------------
// Per layer: CO rows of (NP weight-pairs + 1 bias-word (bias,0)), all u64.
// NP = ceil(CI/2), odd CI padded with 0 in the hi lane.
#define OFF1 0        // L1: 24 * (2+1)  = 72
#define OFF2 72       // L2: 27 * (12+1) = 351
#define OFF3 423      // L3: 27 * (14+1) = 405
#define OFF4 828
#define OFF5 1233
#define OFF6 1638
#define OFF7 2043     // L7:  9 * (14+1) = 135
#define TOTW 2178     // total u64

#define W8S_OFF  (TOTW * 8)            // 17424 bytes
#define HS_OFF   (W8S_OFF + 246 * 4)   // 18408 bytes (8B aligned)
#define HS_PLANE (TIY * TIX)           // 3328 floats per channel
#define SMEM_TOTAL (HS_OFF + 9 * HS_PLANE * 4)   // 138216 bytes

__device__ __forceinline__ void fill_layer(u64* dst, const float* __restrict__ w,
                                           const float* __restrict__ b,
                                           int CI, int CO, int NP, int tid) {
    int n = CO * (NP + 1);
    for (int idx = tid; idx < n; idx += NTHREADS) {
        int o = idx / (NP + 1), c = idx % (NP + 1);
        float lo, hi;
        if (c == NP) { lo = b[o]; hi = 0.0f; }
        else {
            lo = w[o * CI + 2 * c];
            hi = (2 * c + 1 < CI) ? w[o * CI + 2 * c + 1] : 0.0f;
        }
        unsigned int ulo = __float_as_uint(lo), uhi = __float_as_uint(hi);
        dst[idx] = (((u64)uhi) << 32) | ulo;
    }
}

// One pointwise layer for 2 pixels sharing weight loads.
// in0/in1: NP channel-pair u64.  out0/out1: CO scalars.
template <int NP, int CO, bool ACT>
__device__ __forceinline__ void layer(const u64* __restrict__ ws,
                                      const u64* __restrict__ in0,
                                      const u64* __restrict__ in1,
                                      float* __restrict__ out0,
                                      float* __restrict__ out1) {
#pragma unroll
    for (int o = 0; o < CO; o++) {
        const u64* r = ws + o * (NP + 1);
        u64 bw = r[NP];                 // (bias, 0)
        u64 a0 = bw, a1 = bw;
#pragma unroll
        for (int i = 0; i < NP; i++) {
            u64 w = r[i];
            a0 = fma2(in0[i], w, a0);
            a1 = fma2(in1[i], w, a1);
        }
        float s0 = sum2(a0), s1 = sum2(a1);
        out0[o] = ACT ? lrelu(s0) : s0;
        out1[o] = ACT ? lrelu(s1) : s1;
    }
}

// Repack CO scalars into ceil(CO/2) channel-pair u64 (pad hi with 0 if odd).
template <int CO>
__device__ __forceinline__ void repack(const float* __restrict__ s, u64* __restrict__ p) {
#pragma unroll
    for (int j = 0; j < CO / 2; j++) p[j] = pack2(s[2 * j], s[2 * j + 1]);
    if (CO & 1) p[CO / 2] = pack2(s[CO - 1], 0.0f);
}

__global__ void __launch_bounds__(NTHREADS, 1)
fusion_kernel(const float* __restrict__ x,
              const float* __restrict__ w1, const float* __restrict__ b1,
              const float* __restrict__ w2, const float* __restrict__ b2,
              const float* __restrict__ w3, const float* __restrict__ b3,
              const float* __restrict__ w4, const float* __restrict__ b4,
              const float* __restrict__ w5, const float* __restrict__ b5,
              const float* __restrict__ w6, const float* __restrict__ b6,
              const float* __restrict__ w7, const float* __restrict__ b7,
              const float* __restrict__ w8, const float* __restrict__ b8,
              float* __restrict__ out) {
    extern __shared__ char smem[];
    u64*   wsm = (u64*)smem;
    float* w8s = (float*)(smem + W8S_OFF);
    float* hs  = (float*)(smem + HS_OFF);

    const int tid = threadIdx.x;

    fill_layer(wsm + OFF1, w1, b1, 4, 24, 2, tid);
    fill_layer(wsm + OFF2, w2, b2, 24, 27, 12, tid);
    fill_layer(wsm + OFF3, w3, b3, 27, 27, 14, tid);
    fill_layer(wsm + OFF4, w4, b4, 27, 27, 14, tid);
    fill_layer(wsm + OFF5, w5, b5, 27, 27, 14, tid);
    fill_layer(wsm + OFF6, w6, b6, 27, 27, 14, tid);
    fill_layer(wsm + OFF7, w7, b7, 27,  9, 14, tid);
    for (int i = tid; i < 243; i += NTHREADS) w8s[i] = w8[i];
    if (tid < 3) w8s[243 + tid] = b8[tid];
    __syncthreads();

    const int x0 = blockIdx.x * TOX;
    const int y0 = blockIdx.y * TOY;
    const int b  = blockIdx.z;
    const float* xb = x + (size_t)b * 4 * HH * WW;
    const size_t HW = (size_t)HH * WW;

    // ---- pointwise chain: each task = 2 adjacent pixels ----
    const int NPAIRS = (TIX / 2) * TIY;      // 1664
    for (int p = tid; p < NPAIRS; p += NTHREADS) {
        int row = p / (TIX / 2);
        int cp  = p % (TIX / 2);
        int gy = y0 + row, gx = x0 + cp * 2;

        const float* px = xb + (size_t)gy * WW + gx;
        float2 v0 = *(const float2*)(px);
        float2 v1 = *(const float2*)(px + HW);
        float2 v2 = *(const float2*)(px + 2 * HW);
        float2 v3 = *(const float2*)(px + 3 * HW);

        u64 in0[14], in1[14];
        float s0[27], s1[27];

        in0[0] = pack2(v0.x, v1.x); in0[1] = pack2(v2.x, v3.x);
        in1[0] = pack2(v0.y, v1.y); in1[1] = pack2(v2.y, v3.y);

        layer<2, 24, true >(wsm + OFF1, in0, in1, s0, s1);
        repack<24>(s0, in0); repack<24>(s1, in1);
        layer<12, 27, true >(wsm + OFF2, in0, in1, s0, s1);
        repack<27>(s0, in0); repack<27>(s1, in1);
        layer<14, 27, true >(wsm + OFF3, in0, in1, s0, s1);
        repack<27>(s0, in0); repack<27>(s1, in1);
        layer<14, 27, true >(wsm + OFF4, in0, in1, s0, s1);
        repack<27>(s0, in0); repack<27>(s1, in1);
        layer<14, 27, true >(wsm + OFF5, in0, in1, s0, s1);
        repack<27>(s0, in0); repack<27>(s1, in1);
        layer<14, 27, true >(wsm + OFF6, in0, in1, s0, s1);
        repack<27>(s0, in0); repack<27>(s1, in1);
        layer<14, 9, false>(wsm + OFF7, in0, in1, s0, s1);

#pragma unroll
        for (int ch = 0; ch < 9; ch++)
            *(u64*)&hs[ch * HS_PLANE + row * TIX + cp * 2] = pack2(s0[ch], s1[ch]);
    }
    __syncthreads();

    // ---- 3x3 VALID conv 9 -> 3 from SMEM ----
    const size_t obase = (size_t)b * 3 * OH * OW;
    const float bb0 = w8s[243], bb1 = w8s[244], bb2 = w8s[245];
    for (int q = tid; q < TOX * TOY; q += NTHREADS) {
        int oy = q / TOX, ox = q % TOX;
        float a0 = bb0, a1 = bb1, a2 = bb2;
#pragma unroll
        for (int ci = 0; ci < 9; ci++) {
#pragma unroll
            for (int ky = 0; ky < 3; ky++) {
                const float* hp = &hs[ci * HS_PLANE + (oy + ky) * TIX + ox];
#pragma unroll
                for (int kx = 0; kx < 3; kx++) {
                    float v = hp[kx];
                    int wi = (ci * 3 + ky) * 3 + kx;
                    a0 = fmaf(v, w8s[wi], a0);
                    a1 = fmaf(v, w8s[81 + wi], a1);
                    a2 = fmaf(v, w8s[162 + wi], a2);
                }
            }
        }
        int gy = y0 + oy, gx = x0 + ox;
        size_t o = obase + (size_t)gy * OW + gx;
        out[o]                       = a0;
        out[o + (size_t)OH * OW]     = a1;
        out[o + (size_t)2 * OH * OW] = a2;
    }
}

extern "C" void kernel_launch(void* const* d_in, const int* in_sizes, int n_in,
                              void* d_out, int out_size) {
    (void)in_sizes; (void)n_in; (void)out_size;
    const float* x  = (const float*)d_in[0];
    const float* w1 = (const float*)d_in[1];
    const float* b1 = (const float*)d_in[2];
    const float* w2 = (const float*)d_in[3];
    const float* b2 = (const float*)d_in[4];
    const float* w3 = (const float*)d_in[5];
    const float* b3 = (const float*)d_in[6];
    const float* w4 = (const float*)d_in[7];
    const float* b4 = (const float*)d_in[8];
    const float* w5 = (const float*)d_in[9];
    const float* b5 = (const float*)d_in[10];
    const float* w6 = (const float*)d_in[11];
    const float* b6 = (const float*)d_in[12];
    const float* w7 = (const float*)d_in[13];
    const float* b7 = (const float*)d_in[14];
    const float* w8 = (const float*)d_in[15];
    const float* b8 = (const float*)d_in[16];
    float* out = (float*)d_out;

    cudaFuncSetAttribute(fusion_kernel,
                         cudaFuncAttributeMaxDynamicSharedMemorySize, SMEM_TOTAL);
    dim3 grid(OW / TOX, OH / TOY, NB);   // (5, 17, 16)
    fusion_kernel<<<grid, NTHREADS, SMEM_TOTAL>>>(
        x, w1, b1, w2, b2, w3, b3, w4, b4, w5, b5, w6, b6, w7, b7, w8, b8, out);
}

// round 6
// speedup vs baseline: 1.0601x; 1.0464x over previous
#include <cuda_runtime.h>

// ---------------- problem constants ----------------
#define HH 512
#define WW 512
#define NB 16
#define OH 510
#define OW 510

#define TOX 102          // output tile x  (5 * 102 = 510, exact)
#define TOY 30           // output tile y  (17 * 30 = 510, exact)
#define TIX 104          // input tile x (halo +2)
#define TIY 32           // input tile y (halo +2)
#define NTHREADS 256

typedef unsigned long long u64;

// ---------------- packed f32x2 helpers (Blackwell) ----------------
__device__ __forceinline__ u64 fma2(u64 a, u64 b, u64 c) {
    u64 d;
    asm("fma.rn.f32x2 %0, %1, %2, %3;" : "=l"(d) : "l"(a), "l"(b), "l"(c));
    return d;
}
__device__ __forceinline__ u64 add2(u64 a, u64 b) {
    u64 d;
    asm("add.rn.f32x2 %0, %1, %2;" : "=l"(d) : "l"(a), "l"(b));
    return d;
}
__device__ __forceinline__ u64 pack2(float lo, float hi) {
    u64 d;
    asm("mov.b64 %0, {%1, %2};" : "=l"(d) : "f"(lo), "f"(hi));
    return d;
}
__device__ __forceinline__ float sum2(u64 v) {   // lo + hi
    float lo, hi;
    asm("mov.b64 {%0, %1}, %2;" : "=f"(lo), "=f"(hi) : "l"(v));
    return lo + hi;
}
// leaky_relu(s) = 0.55*s + 0.45*|s|  (rel err ~2e-7, verified rounds 2-3)
__device__ __forceinline__ float lrelu(float s) {
    return fmaf(fabsf(s), 0.45f, 0.55f * s);
}

// ---------------- SMEM weight layout (channel-pair packed) ----------------
// Each layer row = NP weight-pairs then the bias pair (b,0), all u64.
#define OFF1 0        // L1: 24 * (2+1)  = 72
#define OFF2 72       // L2: 27 * (12+1) = 351
#define OFF3 423      // L3: 27 * (14+1) = 405
#define OFF4 828
#define OFF5 1233
#define OFF6 1638
#define OFF7 2043     // L7:  9 * (14+1) = 135
#define TOTW 2178     // total u64

#define W8S_OFF  (TOTW * 8)            // 17424 bytes
#define HS_OFF   (W8S_OFF + 246 * 4)   // 18408 bytes (8B aligned)
#define HS_PLANE (TIY * TIX)           // 3328 floats per channel
#define SMEM_TOTAL (HS_OFF + 9 * HS_PLANE * 4)   // 138216 bytes

__device__ __forceinline__ void fill_layer(u64* dst, const float* __restrict__ w,
                                           const float* __restrict__ b,
                                           int CI, int CO, int NP, int tid) {
    int n = CO * (NP + 1);
    for (int idx = tid; idx < n; idx += NTHREADS) {
        int o = idx / (NP + 1), c = idx % (NP + 1);
        float lo, hi;
        if (c == NP) { lo = b[o]; hi = 0.0f; }
        else {
            lo = w[o * CI + 2 * c];
            hi = (2 * c + 1 < CI) ? w[o * CI + 2 * c + 1] : 0.0f;
        }
        unsigned int ulo = __float_as_uint(lo), uhi = __float_as_uint(hi);
        dst[idx] = (((u64)uhi) << 32) | ulo;
    }
}

// One pointwise layer for 2 pixels sharing weight loads.
// 4 independent FMA chains per output channel (lo/hi split per pixel).
template <int NP, int CO, bool ACT>
__device__ __forceinline__ void layer(const u64* __restrict__ ws,
                                      const u64* __restrict__ in0,
                                      const u64* __restrict__ in1,
                                      float* __restrict__ out0,
                                      float* __restrict__ out1) {
    const int NH = NP / 2;               // first-half length (NP may be odd only for NP<... all even here)
#pragma unroll
    for (int o = 0; o < CO; o++) {
        const u64* r = ws + o * (NP + 1);
        u64 bw = r[NP];                  // (bias, 0)
        u64 a0 = bw, a1 = bw;            // chains carrying the bias
        u64 c0 = 0ull, c1 = 0ull;        // second chains
#pragma unroll
        for (int i = 0; i < NH; i++) {
            u64 w = r[i];
            a0 = fma2(in0[i], w, a0);
            a1 = fma2(in1[i], w, a1);
        }
#pragma unroll
        for (int i = NH; i < NP; i++) {
            u64 w = r[i];
            c0 = fma2(in0[i], w, c0);
            c1 = fma2(in1[i], w, c1);
        }
        float s0 = sum2(add2(a0, c0));
        float s1 = sum2(add2(a1, c1));
        out0[o] = ACT ? lrelu(s0) : s0;
        out1[o] = ACT ? lrelu(s1) : s1;
    }
}

// Repack CO scalars into ceil(CO/2) channel-pair u64 (pad hi with 0 if odd).
template <int CO>
__device__ __forceinline__ void repack(const float* __restrict__ s, u64* __restrict__ p) {
#pragma unroll
    for (int j = 0; j < CO / 2; j++) p[j] = pack2(s[2 * j], s[2 * j + 1]);
    if (CO & 1) p[CO / 2] = pack2(s[CO - 1], 0.0f);
}

__global__ void __launch_bounds__(NTHREADS, 1)
fusion_kernel(const float* __restrict__ x,
              const float* __restrict__ w1, const float* __restrict__ b1,
              const float* __restrict__ w2, const float* __restrict__ b2,
              const float* __restrict__ w3, const float* __restrict__ b3,
              const float* __restrict__ w4, const float* __restrict__ b4,
              const float* __restrict__ w5, const float* __restrict__ b5,
              const float* __restrict__ w6, const float* __restrict__ b6,
              const float* __restrict__ w7, const float* __restrict__ b7,
              const float* __restrict__ w8, const float* __restrict__ b8,
              float* __restrict__ out) {
    extern __shared__ char smem[];
    u64*   wsm = (u64*)smem;
    float* w8s = (float*)(smem + W8S_OFF);
    float* hs  = (float*)(smem + HS_OFF);

    const int tid = threadIdx.x;

    fill_layer(wsm + OFF1, w1, b1,  4, 24,  2, tid);
    fill_layer(wsm + OFF2, w2, b2, 24, 27, 12, tid);
    fill_layer(wsm + OFF3, w3, b3, 27, 27, 14, tid);
    fill_layer(wsm + OFF4, w4, b4, 27, 27, 14, tid);
    fill_layer(wsm + OFF5, w5, b5, 27, 27, 14, tid);
    fill_layer(wsm + OFF6, w6, b6, 27, 27, 14, tid);
    fill_layer(wsm + OFF7, w7, b7, 27,  9, 14, tid);
    for (int i = tid; i < 243; i += NTHREADS) w8s[i] = w8[i];
    if (tid < 3) w8s[243 + tid] = b8[tid];
    __syncthreads();

    const int x0 = blockIdx.x * TOX;
    const int y0 = blockIdx.y * TOY;
    const int b  = blockIdx.z;
    const float* xb = x + (size_t)b * 4 * HH * WW;
    const size_t HW = (size_t)HH * WW;

    // ---- pointwise chain: each task = 2 adjacent pixels ----
    const int NPAIRS = (TIX / 2) * TIY;      // 1664
    for (int p = tid; p < NPAIRS; p += NTHREADS) {
        int row = p / (TIX / 2);
        int cp  = p % (TIX / 2);
        int gy = y0 + row, gx = x0 + cp * 2;

        const float* px = xb + (size_t)gy * WW + gx;
        float2 v0 = *(const float2*)(px);
        float2 v1 = *(const float2*)(px + HW);
        float2 v2 = *(const float2*)(px + 2 * HW);
        float2 v3 = *(const float2*)(px + 3 * HW);

        u64 in0[14], in1[14];
        float s0[27], s1[27];

        in0[0] = pack2(v0.x, v1.x); in0[1] = pack2(v2.x, v3.x);
        in1[0] = pack2(v0.y, v1.y); in1[1] = pack2(v2.y, v3.y);

        layer<2, 24, true >(wsm + OFF1, in0, in1, s0, s1);
        repack<24>(s0, in0); repack<24>(s1, in1);
        layer<12, 27, true >(wsm + OFF2, in0, in1, s0, s1);
        repack<27>(s0, in0); repack<27>(s1, in1);
        layer<14, 27, true >(wsm + OFF3, in0, in1, s0, s1);
        repack<27>(s0, in0); repack<27>(s1, in1);
        layer<14, 27, true >(wsm + OFF4, in0, in1, s0, s1);
        repack<27>(s0, in0); repack<27>(s1, in1);
        layer<14, 27, true >(wsm + OFF5, in0, in1, s0, s1);
        repack<27>(s0, in0); repack<27>(s1, in1);
        layer<14, 27, true >(wsm + OFF6, in0, in1, s0, s1);
        repack<27>(s0, in0); repack<27>(s1, in1);
        layer<14, 9, false>(wsm + OFF7, in0, in1, s0, s1);

#pragma unroll
        for (int ch = 0; ch < 9; ch++)
            *(u64*)&hs[ch * HS_PLANE + row * TIX + cp * 2] = pack2(s0[ch], s1[ch]);
    }
    __syncthreads();

    // ---- 3x3 VALID conv 9 -> 3 from SMEM ----
    const size_t obase = (size_t)b * 3 * OH * OW;
    const float bb0 = w8s[243], bb1 = w8s[244], bb2 = w8s[245];
    for (int q = tid; q < TOX * TOY; q += NTHREADS) {
        int oy = q / TOX, ox = q % TOX;
        float a0 = bb0, a1 = bb1, a2 = bb2;
#pragma unroll
        for (int ci = 0; ci < 9; ci++) {
#pragma unroll
            for (int ky = 0; ky < 3; ky++) {
                const float* hp = &hs[ci * HS_PLANE + (oy + ky) * TIX + ox];
#pragma unroll
                for (int kx = 0; kx < 3; kx++) {
                    float v = hp[kx];
                    int wi = (ci * 3 + ky) * 3 + kx;
                    a0 = fmaf(v, w8s[wi], a0);
                    a1 = fmaf(v, w8s[81 + wi], a1);
                    a2 = fmaf(v, w8s[162 + wi], a2);
                }
            }
        }
        int gy = y0 + oy, gx = x0 + ox;
        size_t o = obase + (size_t)gy * OW + gx;
        out[o]                       = a0;
        out[o + (size_t)OH * OW]     = a1;
        out[o + (size_t)2 * OH * OW] = a2;
    }
}

extern "C" void kernel_launch(void* const* d_in, const int* in_sizes, int n_in,
                              void* d_out, int out_size) {
    (void)in_sizes; (void)n_in; (void)out_size;
    const float* x  = (const float*)d_in[0];
    const float* w1 = (const float*)d_in[1];
    const float* b1 = (const float*)d_in[2];
    const float* w2 = (const float*)d_in[3];
    const float* b2 = (const float*)d_in[4];
    const float* w3 = (const float*)d_in[5];
    const float* b3 = (const float*)d_in[6];
    const float* w4 = (const float*)d_in[7];
    const float* b4 = (const float*)d_in[8];
    const float* w5 = (const float*)d_in[9];
    const float* b5 = (const float*)d_in[10];
    const float* w6 = (const float*)d_in[11];
    const float* b6 = (const float*)d_in[12];
    const float* w7 = (const float*)d_in[13];
    const float* b7 = (const float*)d_in[14];
    const float* w8 = (const float*)d_in[15];
    const float* b8 = (const float*)d_in[16];
    float* out = (float*)d_out;

    cudaFuncSetAttribute(fusion_kernel,
                         cudaFuncAttributeMaxDynamicSharedMemorySize, SMEM_TOTAL);
    dim3 grid(OW / TOX, OH / TOY, NB);   // (5, 17, 16)
    fusion_kernel<<<grid, NTHREADS, SMEM_TOTAL>>>(
        x, w1, b1, w2, b2, w3, b3, w4, b4, w5, b5, w6, b6, w7, b7, w8, b8, out);
}

// round 9
// speedup vs baseline: 1.7144x; 1.6172x over previous
#include <cuda_runtime.h>

// ---------------- problem constants ----------------
#define HH 512
#define WW 512
#define NB 16
#define OH 510
#define OW 510
#define HW (HH * WW)              // 262144 = 2^18

#define NTHREADS 256
#define NPP 128                   // pixel-pairs per block (256 pixels)
#define PPW 16                    // pixel-pairs per warp
#define GRID_A (NB * HW / (2 * NPP))   // 16384

typedef unsigned long long u64;

// 9-channel intermediate, NCHW (sanctioned __device__ scratch)
__device__ float g_h[(size_t)NB * 9 * HW];

// ---------------- packed f32x2 helpers ----------------
__device__ __forceinline__ u64 fma2(u64 a, u64 b, u64 c) {
    u64 d;
    asm("fma.rn.f32x2 %0, %1, %2, %3;" : "=l"(d) : "l"(a), "l"(b), "l"(c));
    return d;
}
__device__ __forceinline__ u64 mul2(u64 a, u64 b) {
    u64 d;
    asm("mul.rn.f32x2 %0, %1, %2;" : "=l"(d) : "l"(a), "l"(b));
    return d;
}
__device__ __forceinline__ u64 pack2(float lo, float hi) {
    u64 d;
    asm("mov.b64 %0, {%1, %2};" : "=l"(d) : "f"(lo), "f"(hi));
    return d;
}
// lrelu(x) = 0.55x + 0.45|x| on both packed lanes (rel err ~2e-7, verified)
__device__ __forceinline__ u64 lrelu2(u64 x) {
    const u64 C055 = 0x3F0CCCCD3F0CCCCDull;
    const u64 C045 = 0x3EE666663EE66666ull;
    const u64 MASK = 0x7FFFFFFF7FFFFFFFull;
    return fma2(x & MASK, C045, mul2(x, C055));
}

// ---------------- SMEM layout ----------------
// Weights: per layer CO rows of (CI dup-pairs + dup-bias), row stride CI+1 (u64).
#define OFF1 0        // 24*5   = 120
#define OFF2 120      // 27*25  = 675
#define OFF3 795      // 27*28  = 756
#define OFF4 1551
#define OFF5 2307
#define OFF6 3063
#define OFF7 3819     //  9*28  = 252
#define TOTW 4071

#define PSTR 28                       // u64 stride per pixel-pair in act buffers
#define BUF0_OFF 32576                // after weights (64B aligned)
#define BUF_BYTES (NPP * PSTR * 8)    // 28672
#define BUF1_OFF (BUF0_OFF + BUF_BYTES)
#define SMEM_A (BUF1_OFF + BUF_BYTES) // 89920 bytes

__device__ __forceinline__ void fill_layer(u64* dst, const float* __restrict__ w,
                                           const float* __restrict__ b,
                                           int CI, int CO, int tid) {
    int n = CO * (CI + 1);
    for (int idx = tid; idx < n; idx += NTHREADS) {
        int o = idx / (CI + 1), c = idx % (CI + 1);
        float v = (c < CI) ? w[o * CI + c] : b[o];
        unsigned int u = __float_as_uint(v);
        dst[idx] = (((u64)u) << 32) | u;    // duplicated (v, v)
    }
}

// Mid layer: lane = output channel; weights in registers; acts in SMEM.
template <int CI, int CO, bool ACT>
__device__ __forceinline__ void mlayer(const u64* __restrict__ ws,
                                       const u64* __restrict__ bin,
                                       u64* __restrict__ bout,
                                       int lane, int wid) {
    if (lane < CO) {
        u64 wr[CI + 1];
        const u64* r = ws + lane * (CI + 1);
#pragma unroll
        for (int i = 0; i <= CI; i++) wr[i] = r[i];

        const int pp0 = wid * PPW;
#pragma unroll 1
        for (int t = 0; t < PPW; t += 2) {
            const u64* i0 = bin + (pp0 + t) * PSTR;
            const u64* i1 = i0 + PSTR;
            u64 a0 = wr[CI], a1 = wr[CI];        // (bias, bias)
#pragma unroll
            for (int i = 0; i < CI; i++) {
                a0 = fma2(i0[i], wr[i], a0);
                a1 = fma2(i1[i], wr[i], a1);
            }
            bout[(pp0 + t) * PSTR + lane]     = ACT ? lrelu2(a0) : a0;
            bout[(pp0 + t + 1) * PSTR + lane] = ACT ? lrelu2(a1) : a1;
        }
    }
}

// L7 (27 -> 9, no act): lane = k*9 + o, k = pair-offset 0..2, o = out channel.
__device__ __forceinline__ void l7layer(const u64* __restrict__ ws,
                                        const u64* __restrict__ bin,
                                        u64* __restrict__ bout,
                                        int lane, int wid) {
    if (lane < 27) {
        const int o = lane % 9, k = lane / 9;
        u64 wr[28];
        const u64* r = ws + o * 28;
#pragma unroll
        for (int i = 0; i < 28; i++) wr[i] = r[i];

        const int pp0 = wid * PPW;
#pragma unroll 1
        for (int j = 0; j < (PPW + 2) / 3; j++) {     // 6 passes
            int rel = j * 3 + k;
            if (rel < PPW) {
                const u64* ip = bin + (pp0 + rel) * PSTR;
                u64 a = wr[27];
#pragma unroll
                for (int i = 0; i < 27; i++) a = fma2(ip[i], wr[i], a);
                bout[(pp0 + rel) * PSTR + o] = a;
            }
        }
    }
}

// =================== Kernel A: pointwise chain ===================
__global__ void __launch_bounds__(NTHREADS)
chain_kernel(const float* __restrict__ x,
             const float* __restrict__ w1, const float* __restrict__ b1,
             const float* __restrict__ w2, const float* __restrict__ b2,
             const float* __restrict__ w3, const float* __restrict__ b3,
             const float* __restrict__ w4, const float* __restrict__ b4,
             const float* __restrict__ w5, const float* __restrict__ b5,
             const float* __restrict__ w6, const float* __restrict__ b6,
             const float* __restrict__ w7, const float* __restrict__ b7) {
    extern __shared__ char smem[];
    u64* wsm  = (u64*)smem;
    u64* buf0 = (u64*)(smem + BUF0_OFF);
    u64* buf1 = (u64*)(smem + BUF1_OFF);

    const int tid  = threadIdx.x;
    const int lane = tid & 31;
    const int wid  = tid >> 5;

    fill_layer(wsm + OFF1, w1, b1,  4, 24, tid);
    fill_layer(wsm + OFF2, w2, b2, 24, 27, tid);
    fill_layer(wsm + OFF3, w3, b3, 27, 27, tid);
    fill_layer(wsm + OFF4, w4, b4, 27, 27, tid);
    fill_layer(wsm + OFF5, w5, b5, 27, 27, tid);
    fill_layer(wsm + OFF6, w6, b6, 27, 27, tid);
    fill_layer(wsm + OFF7, w7, b7, 27,  9, tid);

    // ---- stage 256 input pixels (4 ch) as packed pairs ----
    const size_t p0  = (size_t)blockIdx.x * (2 * NPP);
    const size_t b   = p0 >> 18;
    const size_t pix = p0 & (HW - 1);
    const float* xb = x + b * 4 * HW + pix;
    for (int idx = tid; idx < 4 * NPP; idx += NTHREADS) {
        int ch = idx >> 7, pp = idx & (NPP - 1);
        float2 v = *(const float2*)(xb + (size_t)ch * HW + 2 * pp);
        buf0[pp * PSTR + ch] = pack2(v.x, v.y);
    }
    __syncthreads();

    mlayer< 4, 24, true>(wsm + OFF1, buf0, buf1, lane, wid); __syncthreads();
    mlayer<24, 27, true>(wsm + OFF2, buf1, buf0, lane, wid); __syncthreads();
    mlayer<27, 27, true>(wsm + OFF3, buf0, buf1, lane, wid); __syncthreads();
    mlayer<27, 27, true>(wsm + OFF4, buf1, buf0, lane, wid); __syncthreads();
    mlayer<27, 27, true>(wsm + OFF5, buf0, buf1, lane, wid); __syncthreads();
    mlayer<27, 27, true>(wsm + OFF6, buf1, buf0, lane, wid); __syncthreads();
    l7layer(wsm + OFF7, buf0, buf1, lane, wid);              __syncthreads();

    // ---- store 9-channel intermediate (coalesced u64) ----
    float* hb = g_h + b * 9 * HW + pix;
    for (int idx = tid; idx < 9 * NPP; idx += NTHREADS) {
        int ch = idx >> 7, pp = idx & (NPP - 1);
        *(u64*)(hb + (size_t)ch * HW + 2 * pp) = buf1[pp * PSTR + ch];
    }
}

// =================== Kernel B: 3x3 VALID conv 9 -> 3 ===================
#define TBX 34            // 15 * 34 = 510
#define TBY 30            // 17 * 30 = 510
#define IBX 36
#define IBY 32

__global__ void __launch_bounds__(NTHREADS)
conv3_kernel(const float* __restrict__ w8, const float* __restrict__ b8,
             float* __restrict__ out) {
    __shared__ float ht[9][IBY][IBX];     // 41472 B
    __shared__ float w8s[243];
    __shared__ float b8s[3];

    const int tid = threadIdx.x;
    const int x0 = blockIdx.x * TBX;
    const int y0 = blockIdx.y * TBY;
    const int b  = blockIdx.z;

    for (int i = tid; i < 243; i += NTHREADS) w8s[i] = w8[i];
    if (tid < 3) b8s[tid] = b8[tid];

    const float* hb = g_h + (size_t)b * 9 * HW;
    for (int idx = tid; idx < 9 * IBY * IBX; idx += NTHREADS) {
        int ch = idx / (IBY * IBX);
        int r  = (idx / IBX) % IBY;
        int c  = idx % IBX;
        ht[ch][r][c] = hb[(size_t)ch * HW + (size_t)(y0 + r) * WW + (x0 + c)];
    }
    __syncthreads();

    const size_t obase = (size_t)b * 3 * OH * OW;
    for (int q = tid; q < TBX * TBY; q += NTHREADS) {
        int oy = q / TBX, ox = q % TBX;
        float a0 = b8s[0], a1 = b8s[1], a2 = b8s[2];
#pragma unroll
        for (int ci = 0; ci < 9; ci++) {
#pragma unroll
            for (int ky = 0; ky < 3; ky++) {
                const float* hp = &ht[ci][oy + ky][ox];
#pragma unroll
                for (int kx = 0; kx < 3; kx++) {
                    float v = hp[kx];
                    int wi = (ci * 3 + ky) * 3 + kx;
                    a0 = fmaf(v, w8s[wi], a0);
                    a1 = fmaf(v, w8s[81 + wi], a1);
                    a2 = fmaf(v, w8s[162 + wi], a2);
                }
            }
        }
        size_t o = obase + (size_t)(y0 + oy) * OW + (x0 + ox);
        out[o]                       = a0;
        out[o + (size_t)OH * OW]     = a1;
        out[o + (size_t)2 * OH * OW] = a2;
    }
}

extern "C" void kernel_launch(void* const* d_in, const int* in_sizes, int n_in,
                              void* d_out, int out_size) {
    (void)in_sizes; (void)n_in; (void)out_size;
    const float* x  = (const float*)d_in[0];
    const float* w1 = (const float*)d_in[1];
    const float* b1 = (const float*)d_in[2];
    const float* w2 = (const float*)d_in[3];
    const float* b2 = (const float*)d_in[4];
    const float* w3 = (const float*)d_in[5];
    const float* b3 = (const float*)d_in[6];
    const float* w4 = (const float*)d_in[7];
    const float* b4 = (const float*)d_in[8];
    const float* w5 = (const float*)d_in[9];
    const float* b5 = (const float*)d_in[10];
    const float* w6 = (const float*)d_in[11];
    const float* b6 = (const float*)d_in[12];
    const float* w7 = (const float*)d_in[13];
    const float* b7 = (const float*)d_in[14];
    const float* w8 = (const float*)d_in[15];
    const float* b8 = (const float*)d_in[16];
    float* out = (float*)d_out;

    cudaFuncSetAttribute(chain_kernel,
                         cudaFuncAttributeMaxDynamicSharedMemorySize, SMEM_A);
    chain_kernel<<<GRID_A, NTHREADS, SMEM_A>>>(
        x, w1, b1, w2, b2, w3, b3, w4, b4, w5, b5, w6, b6, w7, b7);

    dim3 gridB(OW / TBX, OH / TBY, NB);   // (15, 17, 16)
    conv3_kernel<<<gridB, NTHREADS>>>(w8, b8, out);
}

// round 10
// speedup vs baseline: 1.7762x; 1.0361x over previous
#include <cuda_runtime.h>

// ---------------- problem constants ----------------
#define HH 512
#define WW 512
#define NB 16
#define OH 510
#define OW 510
#define HW (HH * WW)              // 262144 = 2^18

#define NTHREADS 256
#define NPP 128                   // pixel-pairs per block (256 pixels)
#define PPW 16                    // pixel-pairs per warp
#define GRID_A (NB * HW / (2 * NPP))   // 16384

typedef unsigned long long u64;

// 9-channel intermediate, NCHW (sanctioned __device__ scratch)
__device__ float g_h[(size_t)NB * 9 * HW];

// ---------------- packed f32x2 helpers ----------------
__device__ __forceinline__ u64 fma2(u64 a, u64 b, u64 c) {
    u64 d;
    asm("fma.rn.f32x2 %0, %1, %2, %3;" : "=l"(d) : "l"(a), "l"(b), "l"(c));
    return d;
}
__device__ __forceinline__ u64 mul2(u64 a, u64 b) {
    u64 d;
    asm("mul.rn.f32x2 %0, %1, %2;" : "=l"(d) : "l"(a), "l"(b));
    return d;
}
__device__ __forceinline__ u64 pack2(float lo, float hi) {
    u64 d;
    asm("mov.b64 %0, {%1, %2};" : "=l"(d) : "f"(lo), "f"(hi));
    return d;
}
// lrelu(x) = 0.55x + 0.45|x| on both packed lanes (rel err ~2e-7, verified)
__device__ __forceinline__ u64 lrelu2(u64 x) {
    const u64 C055 = 0x3F0CCCCD3F0CCCCDull;
    const u64 C045 = 0x3EE666663EE66666ull;
    const u64 MASK = 0x7FFFFFFF7FFFFFFFull;
    return fma2(x & MASK, C045, mul2(x, C055));
}

// ---------------- SMEM layout ----------------
// Weights: per layer CO rows of (CI dup-pairs + dup-bias), row stride CI+1 (u64).
#define OFF1 0        // 24*5   = 120
#define OFF2 120      // 27*25  = 675
#define OFF3 795      // 27*28  = 756
#define OFF4 1551
#define OFF5 2307
#define OFF6 3063
#define OFF7 3819     //  9*28  = 252
#define TOTW 4071

#define PSTR 28                       // u64 per pixel-pair row (224B, 16B aligned)
#define BUF0_OFF 32576                // after weights (64B aligned)
#define BUF_BYTES (NPP * PSTR * 8)    // 28672
#define BUF1_OFF (BUF0_OFF + BUF_BYTES)
#define SMEM_A (BUF1_OFF + BUF_BYTES) // 89920 bytes

__device__ __forceinline__ void fill_layer(u64* dst, const float* __restrict__ w,
                                           const float* __restrict__ b,
                                           int CI, int CO, int tid) {
    int n = CO * (CI + 1);
    for (int idx = tid; idx < n; idx += NTHREADS) {
        int o = idx / (CI + 1), c = idx % (CI + 1);
        float v = (c < CI) ? w[o * CI + c] : b[o];
        unsigned int u = __float_as_uint(v);
        dst[idx] = (((u64)u) << 32) | u;    // duplicated (v, v)
    }
}

// Mid layer: lane = output channel; weights in regs; acts in SMEM.
// Inputs read as ulonglong2 (LDS.128 broadcast, 2 channels per load).
// ZPAD: lane CO zeroes slot CO so the next layer's odd-CI u2 read is safe.
template <int CI, int CO, bool ACT, bool ZPAD>
__device__ __forceinline__ void mlayer(const u64* __restrict__ ws,
                                       const u64* __restrict__ bin,
                                       u64* __restrict__ bout,
                                       int lane, int wid) {
    const int pp0 = wid * PPW;
    if (lane < CO) {
        constexpr int CIP = (CI + 1) & ~1;          // even: 4,24,28
        u64 wr[CIP];
        const u64* r = ws + lane * (CI + 1);
#pragma unroll
        for (int i = 0; i < CI; i++) wr[i] = r[i];
        if (CIP > CI) wr[CI] = 0ull;
        const u64 bias = r[CI];

#pragma unroll 1
        for (int t = 0; t < PPW; t += 4) {
            const ulonglong2* i0 = (const ulonglong2*)(bin + (pp0 + t) * PSTR);
            const ulonglong2* i1 = (const ulonglong2*)(bin + (pp0 + t + 1) * PSTR);
            const ulonglong2* i2 = (const ulonglong2*)(bin + (pp0 + t + 2) * PSTR);
            const ulonglong2* i3 = (const ulonglong2*)(bin + (pp0 + t + 3) * PSTR);
            u64 a0 = bias, a1 = bias, a2 = bias, a3 = bias;
#pragma unroll
            for (int i = 0; i < CIP / 2; i++) {
                ulonglong2 v0 = i0[i];
                a0 = fma2(v0.x, wr[2 * i], a0);
                a0 = fma2(v0.y, wr[2 * i + 1], a0);
                ulonglong2 v1 = i1[i];
                a1 = fma2(v1.x, wr[2 * i], a1);
                a1 = fma2(v1.y, wr[2 * i + 1], a1);
                ulonglong2 v2 = i2[i];
                a2 = fma2(v2.x, wr[2 * i], a2);
                a2 = fma2(v2.y, wr[2 * i + 1], a2);
                ulonglong2 v3 = i3[i];
                a3 = fma2(v3.x, wr[2 * i], a3);
                a3 = fma2(v3.y, wr[2 * i + 1], a3);
            }
            bout[(pp0 + t) * PSTR + lane]     = ACT ? lrelu2(a0) : a0;
            bout[(pp0 + t + 1) * PSTR + lane] = ACT ? lrelu2(a1) : a1;
            bout[(pp0 + t + 2) * PSTR + lane] = ACT ? lrelu2(a2) : a2;
            bout[(pp0 + t + 3) * PSTR + lane] = ACT ? lrelu2(a3) : a3;
        }
    } else if (ZPAD && lane == CO) {
#pragma unroll 1
        for (int t = 0; t < PPW; t++) bout[(pp0 + t) * PSTR + CO] = 0ull;
    }
}

// L7 (27 -> 9, no act): lane = k*9 + o; k = pair phase 0..2, o = out channel.
__device__ __forceinline__ void l7layer(const u64* __restrict__ ws,
                                        const u64* __restrict__ bin,
                                        u64* __restrict__ bout,
                                        int lane, int wid) {
    if (lane < 27) {
        const int o = lane % 9, k = lane / 9;
        u64 wr[28];
        const u64* r = ws + o * 28;
#pragma unroll
        for (int i = 0; i < 27; i++) wr[i] = r[i];
        wr[27] = 0ull;
        const u64 bias = r[27];
        const int pp0 = wid * PPW;
#pragma unroll 1
        for (int rel = k; rel < PPW; rel += 3) {
            const ulonglong2* ip = (const ulonglong2*)(bin + (pp0 + rel) * PSTR);
            u64 a = bias;
#pragma unroll
            for (int i = 0; i < 14; i++) {
                ulonglong2 v = ip[i];
                a = fma2(v.x, wr[2 * i], a);
                a = fma2(v.y, wr[2 * i + 1], a);
            }
            bout[(pp0 + rel) * PSTR + o] = a;
        }
    }
}

// =================== Kernel A: pointwise chain ===================
__global__ void __launch_bounds__(NTHREADS)
chain_kernel(const float* __restrict__ x,
             const float* __restrict__ w1, const float* __restrict__ b1,
             const float* __restrict__ w2, const float* __restrict__ b2,
             const float* __restrict__ w3, const float* __restrict__ b3,
             const float* __restrict__ w4, const float* __restrict__ b4,
             const float* __restrict__ w5, const float* __restrict__ b5,
             const float* __restrict__ w6, const float* __restrict__ b6,
             const float* __restrict__ w7, const float* __restrict__ b7) {
    extern __shared__ char smem[];
    u64* wsm  = (u64*)smem;
    u64* buf0 = (u64*)(smem + BUF0_OFF);
    u64* buf1 = (u64*)(smem + BUF1_OFF);

    const int tid  = threadIdx.x;
    const int lane = tid & 31;
    const int wid  = tid >> 5;

    fill_layer(wsm + OFF1, w1, b1,  4, 24, tid);
    fill_layer(wsm + OFF2, w2, b2, 24, 27, tid);
    fill_layer(wsm + OFF3, w3, b3, 27, 27, tid);
    fill_layer(wsm + OFF4, w4, b4, 27, 27, tid);
    fill_layer(wsm + OFF5, w5, b5, 27, 27, tid);
    fill_layer(wsm + OFF6, w6, b6, 27, 27, tid);
    fill_layer(wsm + OFF7, w7, b7, 27,  9, tid);

    // ---- stage 256 input pixels (4 ch) as packed pairs ----
    const size_t p0  = (size_t)blockIdx.x * (2 * NPP);
    const size_t b   = p0 >> 18;
    const size_t pix = p0 & (HW - 1);
    const float* xb = x + b * 4 * HW + pix;
    for (int idx = tid; idx < 4 * NPP; idx += NTHREADS) {
        int ch = idx >> 7, pp = idx & (NPP - 1);
        float2 v = *(const float2*)(xb + (size_t)ch * HW + 2 * pp);
        buf0[pp * PSTR + ch] = pack2(v.x, v.y);
    }
    __syncthreads();

    mlayer< 4, 24, true, false>(wsm + OFF1, buf0, buf1, lane, wid); __syncthreads();
    mlayer<24, 27, true, true >(wsm + OFF2, buf1, buf0, lane, wid); __syncthreads();
    mlayer<27, 27, true, true >(wsm + OFF3, buf0, buf1, lane, wid); __syncthreads();
    mlayer<27, 27, true, true >(wsm + OFF4, buf1, buf0, lane, wid); __syncthreads();
    mlayer<27, 27, true, true >(wsm + OFF5, buf0, buf1, lane, wid); __syncthreads();
    mlayer<27, 27, true, true >(wsm + OFF6, buf1, buf0, lane, wid); __syncthreads();
    l7layer(wsm + OFF7, buf0, buf1, lane, wid);                     __syncthreads();

    // ---- store 9-channel intermediate (coalesced u64) ----
    float* hb = g_h + b * 9 * HW + pix;
    for (int idx = tid; idx < 9 * NPP; idx += NTHREADS) {
        int ch = idx >> 7, pp = idx & (NPP - 1);
        *(u64*)(hb + (size_t)ch * HW + 2 * pp) = buf1[pp * PSTR + ch];
    }
}

// =================== Kernel B: 3x3 VALID conv 9 -> 3 ===================
#define TBX 34            // 15 * 34 = 510
#define TBY 30            // 17 * 30 = 510
#define IBX 36
#define IBY 32

__global__ void __launch_bounds__(NTHREADS, 3)
conv3_kernel(const float* __restrict__ w8, const float* __restrict__ b8,
             float* __restrict__ out) {
    __shared__ float ht[9][IBY][IBX];     // 41472 B
    __shared__ float w8s[243];
    __shared__ float b8s[3];

    const int tid = threadIdx.x;
    const int x0 = blockIdx.x * TBX;
    const int y0 = blockIdx.y * TBY;
    const int b  = blockIdx.z;

    for (int i = tid; i < 243; i += NTHREADS) w8s[i] = w8[i];
    if (tid < 3) b8s[tid] = b8[tid];

    const float* hb = g_h + (size_t)b * 9 * HW;
    for (int idx = tid; idx < 9 * IBY * IBX; idx += NTHREADS) {
        int ch = idx / (IBY * IBX);
        int r  = (idx / IBX) % IBY;
        int c  = idx % IBX;
        ht[ch][r][c] = hb[(size_t)ch * HW + (size_t)(y0 + r) * WW + (x0 + c)];
    }
    __syncthreads();

    const size_t obase = (size_t)b * 3 * OH * OW;
    for (int q = tid; q < TBX * TBY; q += NTHREADS) {
        int oy = q / TBX, ox = q % TBX;
        float a0 = b8s[0], a1 = b8s[1], a2 = b8s[2];
#pragma unroll 1
        for (int ci = 0; ci < 9; ci++) {
#pragma unroll
            for (int ky = 0; ky < 3; ky++) {
                const float* hp = &ht[ci][oy + ky][ox];
#pragma unroll
                for (int kx = 0; kx < 3; kx++) {
                    float v = hp[kx];
                    int wi = (ci * 3 + ky) * 3 + kx;
                    a0 = fmaf(v, w8s[wi], a0);
                    a1 = fmaf(v, w8s[81 + wi], a1);
                    a2 = fmaf(v, w8s[162 + wi], a2);
                }
            }
        }
        size_t o = obase + (size_t)(y0 + oy) * OW + (x0 + ox);
        out[o]                       = a0;
        out[o + (size_t)OH * OW]     = a1;
        out[o + (size_t)2 * OH * OW] = a2;
    }
}

extern "C" void kernel_launch(void* const* d_in, const int* in_sizes, int n_in,
                              void* d_out, int out_size) {
    (void)in_sizes; (void)n_in; (void)out_size;
    const float* x  = (const float*)d_in[0];
    const float* w1 = (const float*)d_in[1];
    const float* b1 = (const float*)d_in[2];
    const float* w2 = (const float*)d_in[3];
    const float* b2 = (const float*)d_in[4];
    const float* w3 = (const float*)d_in[5];
    const float* b3 = (const float*)d_in[6];
    const float* w4 = (const float*)d_in[7];
    const float* b4 = (const float*)d_in[8];
    const float* w5 = (const float*)d_in[9];
    const float* b5 = (const float*)d_in[10];
    const float* w6 = (const float*)d_in[11];
    const float* b6 = (const float*)d_in[12];
    const float* w7 = (const float*)d_in[13];
    const float* b7 = (const float*)d_in[14];
    const float* w8 = (const float*)d_in[15];
    const float* b8 = (const float*)d_in[16];
    float* out = (float*)d_out;

    cudaFuncSetAttribute(chain_kernel,
                         cudaFuncAttributeMaxDynamicSharedMemorySize, SMEM_A);
    chain_kernel<<<GRID_A, NTHREADS, SMEM_A>>>(
        x, w1, b1, w2, b2, w3, b3, w4, b4, w5, b5, w6, b6, w7, b7);

    dim3 gridB(OW / TBX, OH / TBY, NB);   // (15, 17, 16)
    conv3_kernel<<<gridB, NTHREADS>>>(w8, b8, out);
}

// round 13
// speedup vs baseline: 1.8864x; 1.0620x over previous
#include <cuda_runtime.h>

// ---------------- problem constants ----------------
#define HH 512
#define WW 512
#define NB 16
#define OH 510
#define OW 510
#define HW (HH * WW)              // 262144 = 2^18

#define NTHREADS 256
#define NPP 128                   // pixel-pairs per block (256 pixels)
#define PPW 16                    // pixel-pairs per warp
#define GRID_A (NB * HW / (2 * NPP))   // 16384

typedef unsigned long long u64;

// 9-channel intermediate, NCHW (sanctioned __device__ scratch)
__device__ float g_h[(size_t)NB * 9 * HW];

// ---------------- packed f32x2 helpers ----------------
__device__ __forceinline__ u64 fma2(u64 a, u64 b, u64 c) {
    u64 d;
    asm("fma.rn.f32x2 %0, %1, %2, %3;" : "=l"(d) : "l"(a), "l"(b), "l"(c));
    return d;
}
__device__ __forceinline__ u64 mul2(u64 a, u64 b) {
    u64 d;
    asm("mul.rn.f32x2 %0, %1, %2;" : "=l"(d) : "l"(a), "l"(b));
    return d;
}
__device__ __forceinline__ u64 pack2(float lo, float hi) {
    u64 d;
    asm("mov.b64 %0, {%1, %2};" : "=l"(d) : "f"(lo), "f"(hi));
    return d;
}
// lrelu(x) = 0.55x + 0.45|x| on both packed lanes (rel err ~2e-7, verified)
__device__ __forceinline__ u64 lrelu2(u64 x) {
    const u64 C055 = 0x3F0CCCCD3F0CCCCDull;
    const u64 C045 = 0x3EE666663EE66666ull;
    const u64 MASK = 0x7FFFFFFF7FFFFFFFull;
    return fma2(x & MASK, C045, mul2(x, C055));
}

// ---------------- SMEM layout ----------------
#define OFF1 0        // 24*5   = 120
#define OFF2 120      // 27*25  = 675
#define OFF3 795      // 27*28  = 756
#define OFF4 1551
#define OFF5 2307
#define OFF6 3063
#define OFF7 3819     //  9*28  = 252
#define TOTW 4071

#define PSTR 28                       // u64 per pixel-pair row (224B, 16B aligned)
#define BUF0_OFF 32576                // after weights (64B aligned)
#define BUF_BYTES (NPP * PSTR * 8)    // 28672
#define BUF1_OFF (BUF0_OFF + BUF_BYTES)
#define SMEM_A (BUF1_OFF + BUF_BYTES) // 89920 bytes (x2 = 175.6 KB fits one SM)

__device__ __forceinline__ void fill_layer(u64* dst, const float* __restrict__ w,
                                           const float* __restrict__ b,
                                           int CI, int CO, int tid) {
    int n = CO * (CI + 1);
    for (int idx = tid; idx < n; idx += NTHREADS) {
        int o = idx / (CI + 1), c = idx % (CI + 1);
        float v = (c < CI) ? w[o * CI + c] : b[o];
        unsigned int u = __float_as_uint(v);
        dst[idx] = (((u64)u) << 32) | u;    // duplicated (v, v)
    }
}

// Mid layer: lane = output channel; weights in regs; acts in SMEM.
// 2 pair-streams per iteration (low transient pressure for the 128-reg cap).
template <int CI, int CO, bool ACT, bool ZPAD>
__device__ __forceinline__ void mlayer(const u64* __restrict__ ws,
                                       const u64* __restrict__ bin,
                                       u64* __restrict__ bout,
                                       int lane, int wid) {
    const int pp0 = wid * PPW;
    if (lane < CO) {
        constexpr int CIP = (CI + 1) & ~1;          // even: 4,24,28
        u64 wr[CIP];
        const u64* r = ws + lane * (CI + 1);
#pragma unroll
        for (int i = 0; i < CI; i++) wr[i] = r[i];
        if (CIP > CI) wr[CI] = 0ull;
        const u64 bias = r[CI];

#pragma unroll 1
        for (int t = 0; t < PPW; t += 2) {
            const ulonglong2* i0 = (const ulonglong2*)(bin + (pp0 + t) * PSTR);
            const ulonglong2* i1 = (const ulonglong2*)(bin + (pp0 + t + 1) * PSTR);
            u64 a0 = bias, a1 = bias;
#pragma unroll
            for (int i = 0; i < CIP / 2; i++) {
                ulonglong2 v0 = i0[i];
                a0 = fma2(v0.x, wr[2 * i], a0);
                a0 = fma2(v0.y, wr[2 * i + 1], a0);
                ulonglong2 v1 = i1[i];
                a1 = fma2(v1.x, wr[2 * i], a1);
                a1 = fma2(v1.y, wr[2 * i + 1], a1);
            }
            bout[(pp0 + t) * PSTR + lane]     = ACT ? lrelu2(a0) : a0;
            bout[(pp0 + t + 1) * PSTR + lane] = ACT ? lrelu2(a1) : a1;
        }
    } else if (ZPAD && lane == CO) {
#pragma unroll 1
        for (int t = 0; t < PPW; t++) bout[(pp0 + t) * PSTR + CO] = 0ull;
    }
}

// L7 (27 -> 9, no act): lane = k*9 + o; k = pair phase 0..2, o = out channel.
__device__ __forceinline__ void l7layer(const u64* __restrict__ ws,
                                        const u64* __restrict__ bin,
                                        u64* __restrict__ bout,
                                        int lane, int wid) {
    if (lane < 27) {
        const int o = lane % 9, k = lane / 9;
        u64 wr[28];
        const u64* r = ws + o * 28;
#pragma unroll
        for (int i = 0; i < 27; i++) wr[i] = r[i];
        wr[27] = 0ull;
        const u64 bias = r[27];
        const int pp0 = wid * PPW;
#pragma unroll 1
        for (int rel = k; rel < PPW; rel += 3) {
            const ulonglong2* ip = (const ulonglong2*)(bin + (pp0 + rel) * PSTR);
            u64 a = bias;
#pragma unroll
            for (int i = 0; i < 14; i++) {
                ulonglong2 v = ip[i];
                a = fma2(v.x, wr[2 * i], a);
                a = fma2(v.y, wr[2 * i + 1], a);
            }
            bout[(pp0 + rel) * PSTR + o] = a;
        }
    }
}

// =================== Kernel A: pointwise chain ===================
__global__ void __launch_bounds__(NTHREADS, 2)
chain_kernel(const float* __restrict__ x,
             const float* __restrict__ w1, const float* __restrict__ b1,
             const float* __restrict__ w2, const float* __restrict__ b2,
             const float* __restrict__ w3, const float* __restrict__ b3,
             const float* __restrict__ w4, const float* __restrict__ b4,
             const float* __restrict__ w5, const float* __restrict__ b5,
             const float* __restrict__ w6, const float* __restrict__ b6,
             const float* __restrict__ w7, const float* __restrict__ b7) {
    extern __shared__ char smem[];
    u64* wsm  = (u64*)smem;
    u64* buf0 = (u64*)(smem + BUF0_OFF);
    u64* buf1 = (u64*)(smem + BUF1_OFF);

    const int tid  = threadIdx.x;
    const int lane = tid & 31;
    const int wid  = tid >> 5;

    fill_layer(wsm + OFF1, w1, b1,  4, 24, tid);
    fill_layer(wsm + OFF2, w2, b2, 24, 27, tid);
    fill_layer(wsm + OFF3, w3, b3, 27, 27, tid);
    fill_layer(wsm + OFF4, w4, b4, 27, 27, tid);
    fill_layer(wsm + OFF5, w5, b5, 27, 27, tid);
    fill_layer(wsm + OFF6, w6, b6, 27, 27, tid);
    fill_layer(wsm + OFF7, w7, b7, 27,  9, tid);

    // ---- stage 256 input pixels (4 ch) as packed pairs ----
    const size_t p0  = (size_t)blockIdx.x * (2 * NPP);
    const size_t b   = p0 >> 18;
    const size_t pix = p0 & (HW - 1);
    const float* xb = x + b * 4 * HW + pix;
    for (int idx = tid; idx < 4 * NPP; idx += NTHREADS) {
        int ch = idx >> 7, pp = idx & (NPP - 1);
        float2 v = *(const float2*)(xb + (size_t)ch * HW + 2 * pp);
        buf0[pp * PSTR + ch] = pack2(v.x, v.y);
    }
    __syncthreads();

    mlayer< 4, 24, true, false>(wsm + OFF1, buf0, buf1, lane, wid); __syncthreads();
    mlayer<24, 27, true, true >(wsm + OFF2, buf1, buf0, lane, wid); __syncthreads();
    mlayer<27, 27, true, true >(wsm + OFF3, buf0, buf1, lane, wid); __syncthreads();
    mlayer<27, 27, true, true >(wsm + OFF4, buf1, buf0, lane, wid); __syncthreads();
    mlayer<27, 27, true, true >(wsm + OFF5, buf0, buf1, lane, wid); __syncthreads();
    mlayer<27, 27, true, true >(wsm + OFF6, buf1, buf0, lane, wid); __syncthreads();
    l7layer(wsm + OFF7, buf0, buf1, lane, wid);                     __syncthreads();

    // ---- store 9-channel intermediate (coalesced u64) ----
    float* hb = g_h + b * 9 * HW + pix;
    for (int idx = tid; idx < 9 * NPP; idx += NTHREADS) {
        int ch = idx >> 7, pp = idx & (NPP - 1);
        *(u64*)(hb + (size_t)ch * HW + 2 * pp) = buf1[pp * PSTR + ch];
    }
}

// =================== Kernel B: 3x3 VALID conv 9 -> 3 ===================
#define TBX 34            // 15 * 34 = 510
#define TBY 30            // 17 * 30 = 510
#define IBX 36
#define IBY 32
#define NPAIRS_B ((TBX / 2) * TBY)    // 510 output-pairs per block

__global__ void __launch_bounds__(NTHREADS, 3)
conv3_kernel(const float* __restrict__ w8, const float* __restrict__ b8,
             float* __restrict__ out) {
    __shared__ float ht[9][IBY][IBX];     // 41472 B
    __shared__ float w8s[243];
    __shared__ float b8s[3];

    const int tid = threadIdx.x;
    const int x0 = blockIdx.x * TBX;
    const int y0 = blockIdx.y * TBY;
    const int b  = blockIdx.z;

    for (int i = tid; i < 243; i += NTHREADS) w8s[i] = w8[i];
    if (tid < 3) b8s[tid] = b8[tid];

    const float* hb = g_h + (size_t)b * 9 * HW;
    for (int idx = tid; idx < 9 * IBY * IBX; idx += NTHREADS) {
        int ch = idx / (IBY * IBX);
        int r  = (idx / IBX) % IBY;
        int c  = idx % IBX;
        ht[ch][r][c] = hb[(size_t)ch * HW + (size_t)(y0 + r) * WW + (x0 + c)];
    }
    __syncthreads();

    const size_t obase = (size_t)b * 3 * OH * OW;
    // 2 adjacent outputs per thread; float2 loads share input across kx.
    for (int q = tid; q < NPAIRS_B; q += NTHREADS) {
        int oy  = q / (TBX / 2);
        int ox  = (q % (TBX / 2)) * 2;
        float a0 = b8s[0], a1 = b8s[1], a2 = b8s[2];        // output x = ox
        float c0 = b8s[0], c1 = b8s[1], c2 = b8s[2];        // output x = ox+1
#pragma unroll 1
        for (int ci = 0; ci < 9; ci++) {
#pragma unroll
            for (int ky = 0; ky < 3; ky++) {
                const float* hp = &ht[ci][oy + ky][ox];      // 8B aligned (ox even)
                float2 vA = *(const float2*)hp;              // x+0, x+1
                float2 vB = *(const float2*)(hp + 2);        // x+2, x+3
                int wi = (ci * 3 + ky) * 3;
                float k0 = w8s[wi],       k1 = w8s[wi + 1],       k2 = w8s[wi + 2];
                float m0 = w8s[81 + wi],  m1 = w8s[82 + wi],      m2 = w8s[83 + wi];
                float n0 = w8s[162 + wi], n1 = w8s[163 + wi],     n2 = w8s[164 + wi];
                a0 = fmaf(vA.x, k0, a0); a0 = fmaf(vA.y, k1, a0); a0 = fmaf(vB.x, k2, a0);
                a1 = fmaf(vA.x, m0, a1); a1 = fmaf(vA.y, m1, a1); a1 = fmaf(vB.x, m2, a1);
                a2 = fmaf(vA.x, n0, a2); a2 = fmaf(vA.y, n1, a2); a2 = fmaf(vB.x, n2, a2);
                c0 = fmaf(vA.y, k0, c0); c0 = fmaf(vB.x, k1, c0); c0 = fmaf(vB.y, k2, c0);
                c1 = fmaf(vA.y, m0, c1); c1 = fmaf(vB.x, m1, c1); c1 = fmaf(vB.y, m2, c1);
                c2 = fmaf(vA.y, n0, c2); c2 = fmaf(vB.x, n1, c2); c2 = fmaf(vB.y, n2, c2);
            }
        }
        size_t o = obase + (size_t)(y0 + oy) * OW + (x0 + ox);
        out[o]                           = a0;
        out[o + 1]                       = c0;
        out[o + (size_t)OH * OW]         = a1;
        out[o + (size_t)OH * OW + 1]     = c1;
        out[o + (size_t)2 * OH * OW]     = a2;
        out[o + (size_t)2 * OH * OW + 1] = c2;
    }
}

extern "C" void kernel_launch(void* const* d_in, const int* in_sizes, int n_in,
                              void* d_out, int out_size) {
    (void)in_sizes; (void)n_in; (void)out_size;
    const float* x  = (const float*)d_in[0];
    const float* w1 = (const float*)d_in[1];
    const float* b1 = (const float*)d_in[2];
    const float* w2 = (const float*)d_in[3];
    const float* b2 = (const float*)d_in[4];
    const float* w3 = (const float*)d_in[5];
    const float* b3 = (const float*)d_in[6];
    const float* w4 = (const float*)d_in[7];
    const float* b4 = (const float*)d_in[8];
    const float* w5 = (const float*)d_in[9];
    const float* b5 = (const float*)d_in[10];
    const float* w6 = (const float*)d_in[11];
    const float* b6 = (const float*)d_in[12];
    const float* w7 = (const float*)d_in[13];
    const float* b7 = (const float*)d_in[14];
    const float* w8 = (const float*)d_in[15];
    const float* b8 = (const float*)d_in[16];
    float* out = (float*)d_out;

    cudaFuncSetAttribute(chain_kernel,
                         cudaFuncAttributeMaxDynamicSharedMemorySize, SMEM_A);
    chain_kernel<<<GRID_A, NTHREADS, SMEM_A>>>(
        x, w1, b1, w2, b2, w3, b3, w4, b4, w5, b5, w6, b6, w7, b7);

    dim3 gridB(OW / TBX, OH / TBY, NB);   // (15, 17, 16)
    conv3_kernel<<<gridB, NTHREADS>>>(w8, b8, out);
}